// round 16
// baseline (speedup 1.0000x reference)
#include <cuda_runtime.h>

#define BB 64
#define PP 8732
#define CC 81
#define OO 32
#define NBLK1 35            // ceil(PP/256) match chunks per batch

// kA tiling: persistent, 3-stage TMA pipeline, 7 blocks/SM
#define TROWS 32
#define NTILES ((BB*PP)/TROWS)     // 17464
#define GRID_A (148*7)             // 1036 blocks = 7/SM, 56 warps/SM
#define TPA 256
#define TILE_B (TROWS*CC*4)        // 10368 bytes per tile

// ---------------- scratch (static device globals; no allocation) ----------------
__device__ float g_ov[BB*PP];
__device__ int   g_oi[BB*PP];
__device__ unsigned g_key[BB*PP];                  // orderable-uint CE keys
__device__ unsigned long long g_part[NBLK1*BB*OO]; // per-chunk argmax partials
__device__ float g_loc_sum;
__device__ int   g_npos;
__device__ float g_cepos;
__device__ float g_hard;
__device__ int   g_done;

// ---------------- helpers ----------------
__device__ __forceinline__ unsigned order_key(float f) {
    unsigned u = __float_as_uint(f);
    return (u & 0x80000000u) ? ~u : (u | 0x80000000u);
}
__device__ __forceinline__ float key_val(unsigned u) {
    u = (u & 0x80000000u) ? (u & 0x7FFFFFFFu) : ~u;
    return __uint_as_float(u);
}
__device__ __forceinline__ void mbar_init(unsigned addr, unsigned cnt) {
    asm volatile("mbarrier.init.shared.b64 [%0], %1;" :: "r"(addr), "r"(cnt) : "memory");
}
__device__ __forceinline__ void mbar_expect_tx(unsigned addr, unsigned bytes) {
    asm volatile("mbarrier.arrive.expect_tx.shared.b64 _, [%0], %1;"
                 :: "r"(addr), "r"(bytes) : "memory");
}
__device__ __forceinline__ void bulk_g2s(unsigned dst, const void* src,
                                         unsigned bytes, unsigned mbar) {
    asm volatile("cp.async.bulk.shared::cta.global.mbarrier::complete_tx::bytes "
                 "[%0], [%1], %2, [%3];"
                 :: "r"(dst), "l"(src), "r"(bytes), "r"(mbar) : "memory");
}
__device__ __forceinline__ void mbar_wait(unsigned addr, unsigned parity) {
    unsigned done;
    asm volatile(
        "{\n\t.reg .pred p;\n\t"
        "mbarrier.try_wait.parity.acquire.cta.shared::cta.b64 p, [%1], %2;\n\t"
        "selp.b32 %0, 1, 0, p;\n\t}"
        : "=r"(done) : "r"(addr), "r"(parity) : "memory");
    while (!done) {
        __nanosleep(32);
        asm volatile(
            "{\n\t.reg .pred p;\n\t"
            "mbarrier.try_wait.parity.acquire.cta.shared::cta.b64 p, [%1], %2;\n\t"
            "selp.b32 %0, 1, 0, p;\n\t}"
            : "=r"(done) : "r"(addr), "r"(parity) : "memory");
    }
}

// ---------------- k1: IoU matching, ballot object-side argmax -------------------
__global__ void __launch_bounds__(256) k1_match(
        const float* __restrict__ tb, const float* __restrict__ pbx,
        const float* __restrict__ scores) {
    int b  = blockIdx.x / NBLK1;
    int bx = blockIdx.x - b * NBLK1;
    int p  = bx * 256 + threadIdx.x;
    int tid = threadIdx.x;

    // one L2 prefetch line per thread (neutral in R13; keep)
    {
        size_t gid = (size_t)blockIdx.x * 256 + tid;
        asm volatile("prefetch.global.L2 [%0];"
                     :: "l"((const char*)scores + gid * 128));
    }

    __shared__ float mx0[OO], my0[OO], mx1[OO], my1[OO], marea[OO];
    __shared__ unsigned long long mbest[OO];
    if (tid < OO) {
        const float* t4 = tb + (size_t)(b*OO + tid) * 4;
        float x0 = t4[0], y0 = t4[1], x1 = t4[2], y1 = t4[3];
        mx0[tid] = x0; my0[tid] = y0; mx1[tid] = x1; my1[tid] = y1;
        marea[tid] = (x1 - x0) * (y1 - y0);
        mbest[tid] = 0ULL;
    }
    __syncthreads();

    bool valid = (p < PP);
    float bx0 = 0, by0 = 0, bx1 = 0, by1 = 0, areab = 0;
    if (valid) {
        const float* pr = pbx + (size_t)p * 4;
        float cx = pr[0], cy = pr[1], w = pr[2], h = pr[3];
        bx0 = cx - 0.5f * w; bx1 = cx + 0.5f * w;
        by0 = cy - 0.5f * h; by1 = cy + 0.5f * h;
        areab = w * h;
    }
    float bestv = -1.f; int besti = 0;
    int lane = tid & 31;
    unsigned plow = 0xFFFFFFFFu - (unsigned)p;       // smaller p -> larger low bits
    #pragma unroll 4
    for (int o = 0; o < OO; o++) {
        float iou = -1.f;
        if (valid) {
            float lx = fmaxf(mx0[o], bx0), ly = fmaxf(my0[o], by0);
            float rx = fminf(mx1[o], bx1), ry = fminf(my1[o], by1);
            float iw = fmaxf(rx - lx, 0.f), ih = fmaxf(ry - ly, 0.f);
            float inter = iw * ih;
            float uni = marea[o] + areab - inter;
            iou = __fdividef(inter, uni);
            if (iou > bestv) { bestv = iou; besti = o; } // first-index tiebreak
        }
        // warp float max + ballot: one key-build + one smem atomic per warp per o
        float v = iou;
        #pragma unroll
        for (int off = 16; off; off >>= 1)
            v = fmaxf(v, __shfl_xor_sync(0xffffffffu, v, off));
        unsigned m = __ballot_sync(0xffffffffu, iou == v);
        int src = __ffs(m) - 1;                      // lowest lane = smallest prior
        if (lane == src && v >= 0.f) {
            unsigned long long key =
                ((unsigned long long)(__float_as_uint(v) | 0x80000000u) << 32)
                | (unsigned long long)plow;          // smaller p wins global ties
            atomicMax(&mbest[o], key);               // 8 atomics per o per block
        }
    }
    if (valid) { g_ov[b*PP + p] = bestv; g_oi[b*PP + p] = besti; }
    __syncthreads();
    if (tid < OO)
        g_part[((size_t)bx * BB + b) * OO + tid] = mbest[tid];
}

// ---------------- kB: reduce partials + sequential scatter + zero scalars -------
__global__ void kB_scatter() {
    if (blockIdx.x == 0 && threadIdx.x == 0) {
        g_loc_sum = 0.f; g_npos = 0; g_cepos = 0.f; g_hard = 0.f; g_done = 0;
    }
    int w = (blockIdx.x * blockDim.x + threadIdx.x) >> 5;
    int o = threadIdx.x & 31;
    if (w >= BB) return;
    int b = w;
    unsigned long long best = 0ULL;
    #pragma unroll 5
    for (int i = 0; i < NBLK1; i++) {
        unsigned long long k = g_part[((size_t)i * BB + b) * OO + o];
        if (k > best) best = k;
    }
    #pragma unroll
    for (int j = 0; j < OO; j++) {
        unsigned long long key = __shfl_sync(0xffffffffu, best, j);
        if (o == 0) {
            unsigned p = 0xFFFFFFFFu - (unsigned)(key & 0xFFFFFFFFull);
            if (p < PP) { g_oi[b*PP + p] = j; g_ov[b*PP + p] = 1.0f; }
        }
    }
}

// ---------------- kA: persistent CE, 3-stage TMA pipeline, 7 blocks/SM ----------
// 1036 blocks x 256, 8 threads/row, tiles of 32 rows. TMA keeps per-iteration
// copy cost ~2 instructions, so the smaller tile doesn't pay R12's LDGSTS tax.
__global__ void __launch_bounds__(TPA, 7) kA_ce(
        const float* __restrict__ scores, const float* __restrict__ pred,
        const float* __restrict__ tb, const int* __restrict__ tc,
        const float* __restrict__ pbx) {
    __shared__ alignas(128) float buf[3][TROWS * CC];   // 3 x 10368 B
    __shared__ alignas(8) unsigned long long mbar[3];
    __shared__ float racc[8], rl1[8]; __shared__ int rcnt[8];
    int tid = threadIdx.x;
    int bid = blockIdx.x;
    int part = tid & 7;         // eighth within row
    int r = tid >> 3;           // row within tile (0..31)

    unsigned mb[3], sb[3];
    #pragma unroll
    for (int s = 0; s < 3; s++) {
        mb[s] = (unsigned)__cvta_generic_to_shared(&mbar[s]);
        sb[s] = (unsigned)__cvta_generic_to_shared(buf[s]);
    }
    if (tid == 0) {
        mbar_init(mb[0], 1); mbar_init(mb[1], 1); mbar_init(mb[2], 1);
    }
    __syncthreads();

    // prologue: 3 stages in flight (bid + {0,1,2}*GRID_A all < NTILES)
    if (tid == 0) {
        #pragma unroll
        for (int s = 0; s < 3; s++) {
            int t = bid + s * GRID_A;
            mbar_expect_tx(mb[s], TILE_B);
            bulk_g2s(sb[s], (const char*)scores + (size_t)t * TILE_B, TILE_B, mb[s]);
        }
    }

    float acc = 0.f, l1 = 0.f; int cnt = 0;
    int ph0 = 0, ph1 = 0, ph2 = 0;
    int s = 0;
    for (int t = bid; t < NTILES; t += GRID_A) {
        int phs = (s == 0) ? ph0 : (s == 1) ? ph1 : ph2;
        mbar_wait(mb[s], phs);
        if (s == 0) ph0 ^= 1; else if (s == 1) ph1 ^= 1; else ph2 ^= 1;

        const float* my = buf[s] + r * CC;
        int base = part * 10;
        float a0 = 0.f, a1 = 0.f;
        #pragma unroll
        for (int j = 0; j < 10; j += 2) {
            a0 += __expf(my[base + j]);
            a1 += __expf(my[base + j + 1]);
        }
        float e = a0 + a1;
        if (part == 7) e += __expf(my[80]);
        e += __shfl_xor_sync(0xffffffffu, e, 1);
        e += __shfl_xor_sync(0xffffffffu, e, 2);
        e += __shfl_xor_sync(0xffffffffu, e, 4);   // full row sum in all 8 parts

        if (part == 0) {
            int idx = t * TROWS + r;
            float ov = g_ov[idx];
            int   oi = g_oi[idx];
            int b = idx / PP;
            int p = idx - b * PP;
            int lab = (ov < 0.5f) ? 0 : __ldg(tc + b*OO + oi);
            float ce = __logf(e) - my[lab];
            g_key[idx] = order_key(ce);
            if (lab != 0) {
                acc += ce; cnt++;
                const float* t4 = tb + (size_t)(b*OO + oi) * 4;
                float x0 = __ldg(t4), y0 = __ldg(t4+1), x1 = __ldg(t4+2), y1 = __ldg(t4+3);
                const float* pr = pbx + (size_t)p * 4;
                float pcx = __ldg(pr), pcy = __ldg(pr+1), pw = __ldg(pr+2), phh = __ldg(pr+3);
                float gcx = ((x0 + x1) * 0.5f - pcx) * 10.f / pw;
                float gcy = ((y0 + y1) * 0.5f - pcy) * 10.f / phh;
                float gw  = logf((x1 - x0) / pw) * 5.f;
                float gh  = logf((y1 - y0) / phh) * 5.f;
                const float* pd = pred + (size_t)idx * 4;
                l1 += fabsf(pd[0]-gcx) + fabsf(pd[1]-gcy) + fabsf(pd[2]-gw) + fabsf(pd[3]-gh);
            }
        }
        __syncthreads();               // all threads done reading buf[s]
        int t3 = t + 3 * GRID_A;
        if (t3 < NTILES && tid == 0) { // re-arm stage s
            mbar_expect_tx(mb[s], TILE_B);
            bulk_g2s(sb[s], (const char*)scores + (size_t)t3 * TILE_B, TILE_B, mb[s]);
        }
        s = (s == 2) ? 0 : s + 1;
    }

    // block reduce once at the end
    int lane = tid & 31, wid = tid >> 5;
    #pragma unroll
    for (int off = 16; off; off >>= 1) {
        acc += __shfl_xor_sync(0xffffffffu, acc, off);
        l1  += __shfl_xor_sync(0xffffffffu, l1, off);
        cnt += __shfl_xor_sync(0xffffffffu, cnt, off);
    }
    if (lane == 0) { racc[wid] = acc; rl1[wid] = l1; rcnt[wid] = cnt; }
    __syncthreads();
    if (tid == 0) {
        float a = 0.f, l = 0.f; int c = 0;
        #pragma unroll
        for (int j = 0; j < 8; j++) { a += racc[j]; l += rl1[j]; c += rcnt[j]; }
        if (a != 0.f) atomicAdd(&g_cepos, a);
        if (l != 0.f) atomicAdd(&g_loc_sum, l);
        if (c)        atomicAdd(&g_npos, c);
    }
}

// ---------------- kD: per-row top-k via radix select + fused finalize -----------
__global__ void __launch_bounds__(1024) kD_select(float* __restrict__ out) {
    __shared__ unsigned skeys[PP];
    __shared__ int bins[256];
    __shared__ unsigned sh_pref;
    __shared__ int sh_rem;
    __shared__ float swsum[32];
    __shared__ int swcnt[32];
    int r = blockIdx.x;
    int tid = threadIdx.x;
    const int bd = 1024;
    int lane = tid & 31, wid = tid >> 5;

    {   // uint4 loads: PP = 4*2183
        const uint4* src = (const uint4*)(g_key + (size_t)r * PP);
        uint4* dst = (uint4*)skeys;
        for (int i = tid; i < PP/4; i += bd) dst[i] = src[i];
    }
    __syncthreads();
    int np = g_npos;
    long long k = 3LL * (long long)np;
    const int NITER = (PP + bd - 1) / bd;    // 9 padded iterations (warp-uniform)

    float total = 0.f;
    if (k >= PP) {
        float sv = 0.f;
        for (int p = tid; p < PP; p += bd) sv += key_val(skeys[p]);
        #pragma unroll
        for (int off = 16; off; off >>= 1) sv += __shfl_xor_sync(0xffffffffu, sv, off);
        if (lane == 0) swsum[wid] = sv;
        __syncthreads();
        if (tid == 0) for (int i = 0; i < 32; i++) total += swsum[i];
    } else if (k > 0) {
        unsigned prefix = 0; int rem = (int)k;
        for (int shift = 24; shift >= 0; shift -= 8) {
            if (tid < 256) bins[tid] = 0;
            __syncthreads();
            unsigned hi_mask = (shift == 24) ? 0u : (0xFFFFFFFFu << (shift + 8));
            for (int it = 0; it < NITER; it++) {
                int p = tid + it * bd;
                bool in = (p < PP);
                unsigned key = in ? skeys[p] : 0u;
                bool act = in && ((key & hi_mask) == prefix);
                unsigned bm = __ballot_sync(0xffffffffu, act);
                if (act) {
                    unsigned bin = (key >> shift) & 255u;
                    unsigned peers = __match_any_sync(bm, bin);
                    int leader = __ffs(peers) - 1;
                    if (lane == leader) atomicAdd(&bins[bin], __popc(peers));
                }
            }
            __syncthreads();
            if (tid < 32) {                       // warp-0 suffix scan, 8 bins/lane
                int v[8]; int t = 0;
                #pragma unroll
                for (int j = 0; j < 8; j++) { v[j] = bins[tid*8 + j]; t += v[j]; }
                int run = t;
                #pragma unroll
                for (int off = 1; off < 32; off <<= 1) {
                    int x = __shfl_down_sync(0xffffffffu, run, off);
                    if (tid + off < 32) run += x;
                }
                int c = run - t;                  // suffix over lanes > tid
                #pragma unroll
                for (int j = 7; j >= 0; j--) {
                    int prev = c;
                    c += v[j];
                    if (c >= rem && prev < rem) { // exactly one (lane,j) fires
                        sh_pref = prefix | ((unsigned)(tid*8 + j) << shift);
                        sh_rem  = rem - prev;
                    }
                }
            }
            __syncthreads();
            prefix = sh_pref; rem = sh_rem;
            __syncthreads();
        }
        unsigned kth = prefix;  // exact k-th largest key
        float sumv = 0.f; int cgt = 0;
        for (int p = tid; p < PP; p += bd) {
            unsigned key = skeys[p];
            if (key > kth) { sumv += key_val(key); cgt++; }
        }
        #pragma unroll
        for (int off = 16; off; off >>= 1) {
            sumv += __shfl_xor_sync(0xffffffffu, sumv, off);
            cgt  += __shfl_xor_sync(0xffffffffu, cgt, off);
        }
        if (lane == 0) { swsum[wid] = sumv; swcnt[wid] = cgt; }
        __syncthreads();
        if (tid == 0) {
            float t = 0.f; int c = 0;
            for (int i = 0; i < 32; i++) { t += swsum[i]; c += swcnt[i]; }
            total = t + (float)(k - c) * key_val(kth);   // exact tie handling
        }
    }

    if (tid == 0) {
        if (total != 0.f) atomicAdd(&g_hard, total);
        __threadfence();
        int ticket = atomicAdd(&g_done, 1);
        if (ticket == BB - 1) {                          // last block finalizes
            float hard = *(volatile float*)&g_hard;
            float npf = (float)np;
            out[0] = g_loc_sum / (npf * 4.f) + (g_cepos + hard) / npf;
        }
    }
}

// ---------------- launch ----------------
extern "C" void kernel_launch(void* const* d_in, const int* in_sizes, int n_in,
                              void* d_out, int out_size) {
    const float* pred_boxes   = (const float*)d_in[0];
    const float* pred_scores  = (const float*)d_in[1];
    const float* true_boxes   = (const float*)d_in[2];
    const int*   true_classes = (const int*)d_in[3];
    const float* pboxes       = (const float*)d_in[4];
    float* out = (float*)d_out;
    (void)in_sizes; (void)n_in; (void)out_size;

    k1_match<<<BB*NBLK1, 256>>>(true_boxes, pboxes, pred_scores);
    kB_scatter<<<2, 1024>>>();
    kA_ce<<<GRID_A, TPA>>>(pred_scores, pred_boxes, true_boxes, true_classes, pboxes);
    kD_select<<<BB, 1024>>>(out);
}

// round 17
// speedup vs baseline: 1.1048x; 1.1048x over previous
#include <cuda_runtime.h>

#define BB 64
#define PP 8732
#define CC 81
#define OO 32
#define NBLK1 35            // ceil(PP/256) match chunks per batch

// kA tiling: persistent single wave, double-buffered TMA (R15 shape)
#define TROWS 64
#define NTILES ((BB*PP)/TROWS)     // 8732
#define GRID_A 740                 // 5 blocks/SM x 148 SMs = one wave
#define TPA 256
#define TILE_B (TROWS*CC*4)        // 20736 bytes per tile

// ---------------- scratch (static device globals; no allocation) ----------------
__device__ float g_ov[BB*PP];
__device__ int   g_oi[BB*PP];
__device__ int   g_lab[BB*PP];                     // labels (computed in kC)
__device__ unsigned g_key[BB*PP];                  // orderable-uint CE keys
__device__ unsigned long long g_part[NBLK1*BB*OO]; // per-chunk argmax partials
__device__ float g_loc_sum;
__device__ int   g_npos;
__device__ float g_cepos;
__device__ float g_hard;
__device__ int   g_done;

// ---------------- helpers ----------------
__device__ __forceinline__ unsigned order_key(float f) {
    unsigned u = __float_as_uint(f);
    return (u & 0x80000000u) ? ~u : (u | 0x80000000u);
}
__device__ __forceinline__ float key_val(unsigned u) {
    u = (u & 0x80000000u) ? (u & 0x7FFFFFFFu) : ~u;
    return __uint_as_float(u);
}
__device__ __forceinline__ void mbar_init(unsigned addr, unsigned cnt) {
    asm volatile("mbarrier.init.shared.b64 [%0], %1;" :: "r"(addr), "r"(cnt) : "memory");
}
__device__ __forceinline__ void mbar_expect_tx(unsigned addr, unsigned bytes) {
    asm volatile("mbarrier.arrive.expect_tx.shared.b64 _, [%0], %1;"
                 :: "r"(addr), "r"(bytes) : "memory");
}
__device__ __forceinline__ void bulk_g2s(unsigned dst, const void* src,
                                         unsigned bytes, unsigned mbar) {
    asm volatile("cp.async.bulk.shared::cta.global.mbarrier::complete_tx::bytes "
                 "[%0], [%1], %2, [%3];"
                 :: "r"(dst), "l"(src), "r"(bytes), "r"(mbar) : "memory");
}
__device__ __forceinline__ void mbar_wait(unsigned addr, unsigned parity) {
    unsigned done;
    asm volatile(
        "{\n\t.reg .pred p;\n\t"
        "mbarrier.try_wait.parity.acquire.cta.shared::cta.b64 p, [%1], %2;\n\t"
        "selp.b32 %0, 1, 0, p;\n\t}"
        : "=r"(done) : "r"(addr), "r"(parity) : "memory");
    while (!done) {
        __nanosleep(32);
        asm volatile(
            "{\n\t.reg .pred p;\n\t"
            "mbarrier.try_wait.parity.acquire.cta.shared::cta.b64 p, [%1], %2;\n\t"
            "selp.b32 %0, 1, 0, p;\n\t}"
            : "=r"(done) : "r"(addr), "r"(parity) : "memory");
    }
}

// ---------------- k1: IoU matching (2240 blocks x 256) — exact R15 --------------
__global__ void __launch_bounds__(256) k1_match(
        const float* __restrict__ tb, const float* __restrict__ pbx,
        const float* __restrict__ scores) {
    int b  = blockIdx.x / NBLK1;
    int bx = blockIdx.x - b * NBLK1;
    int p  = bx * 256 + threadIdx.x;
    int tid = threadIdx.x;

    {   // one L2 prefetch line per thread (neutral; harmless)
        size_t gid = (size_t)blockIdx.x * 256 + tid;
        asm volatile("prefetch.global.L2 [%0];"
                     :: "l"((const char*)scores + gid * 128));
    }

    __shared__ float mx0[OO], my0[OO], mx1[OO], my1[OO], marea[OO];
    __shared__ unsigned long long mbest[OO];
    if (tid < OO) {
        const float* t4 = tb + (size_t)(b*OO + tid) * 4;
        float x0 = t4[0], y0 = t4[1], x1 = t4[2], y1 = t4[3];
        mx0[tid] = x0; my0[tid] = y0; mx1[tid] = x1; my1[tid] = y1;
        marea[tid] = (x1 - x0) * (y1 - y0);
        mbest[tid] = 0ULL;
    }
    __syncthreads();
    if (p < PP) {
        const float* pr = pbx + (size_t)p * 4;
        float cx = pr[0], cy = pr[1], w = pr[2], h = pr[3];
        float bx0 = cx - 0.5f * w, bx1 = cx + 0.5f * w;
        float by0 = cy - 0.5f * h, by1 = cy + 0.5f * h;
        float areab = w * h;
        float bestv = -1.f; int besti = 0;
        unsigned plow = 0xFFFFFFFFu - (unsigned)p;       // smaller p -> larger low bits
        #pragma unroll 4
        for (int o = 0; o < OO; o++) {
            float lx = fmaxf(mx0[o], bx0), ly = fmaxf(my0[o], by0);
            float rx = fminf(mx1[o], bx1), ry = fminf(my1[o], by1);
            float iw = fmaxf(rx - lx, 0.f), ih = fmaxf(ry - ly, 0.f);
            float inter = iw * ih;
            float uni = marea[o] + areab - inter;
            float iou = __fdividef(inter, uni);
            if (iou > bestv) { bestv = iou; besti = o; } // first-index tiebreak
            unsigned long long key =
                ((unsigned long long)(__float_as_uint(iou) | 0x80000000u) << 32)
                | (unsigned long long)plow;              // smaller p wins ties
            if (key > mbest[o]) atomicMax(&mbest[o], key); // guard makes atomics rare
        }
        g_ov[b*PP + p] = bestv;
        g_oi[b*PP + p] = besti;
    }
    __syncthreads();
    if (tid < OO)
        g_part[((size_t)bx * BB + b) * OO + tid] = mbest[tid];
}

// ---------------- kB: reduce partials + sequential scatter + zero scalars -------
__global__ void kB_scatter() {
    if (blockIdx.x == 0 && threadIdx.x == 0) {
        g_loc_sum = 0.f; g_npos = 0; g_cepos = 0.f; g_hard = 0.f; g_done = 0;
    }
    int w = (blockIdx.x * blockDim.x + threadIdx.x) >> 5;
    int o = threadIdx.x & 31;
    if (w >= BB) return;
    int b = w;
    unsigned long long best = 0ULL;
    #pragma unroll 5
    for (int i = 0; i < NBLK1; i++) {
        unsigned long long k = g_part[((size_t)i * BB + b) * OO + o];
        if (k > best) best = k;
    }
    #pragma unroll
    for (int j = 0; j < OO; j++) {
        unsigned long long key = __shfl_sync(0xffffffffu, best, j);
        if (o == 0) {
            unsigned p = 0xFFFFFFFFu - (unsigned)(key & 0xFFFFFFFFull);
            if (p < PP) { g_oi[b*PP + p] = j; g_ov[b*PP + p] = 1.0f; }
        }
    }
}

// ---------------- kC: labels + loc loss + n_pos (thread per row) ----------------
// Runs after scatter. Removes the dependent-load chain from kA's hot loop.
__global__ void __launch_bounds__(256) kC_label(
        const float* __restrict__ pred, const int* __restrict__ tc,
        const float* __restrict__ tb, const float* __restrict__ pbx) {
    int idx = blockIdx.x * 256 + threadIdx.x;      // 2183*256 == BB*PP exactly
    float ov = g_ov[idx];
    int   oi = g_oi[idx];
    int b = idx / PP;
    int p = idx - b * PP;
    int lab = (ov < 0.5f) ? 0 : __ldg(tc + b*OO + oi);
    g_lab[idx] = lab;

    float l1 = 0.f; int cnt = 0;
    if (lab != 0) {
        cnt = 1;
        const float* t4 = tb + (size_t)(b*OO + oi) * 4;
        float x0 = __ldg(t4), y0 = __ldg(t4+1), x1 = __ldg(t4+2), y1 = __ldg(t4+3);
        const float* pr = pbx + (size_t)p * 4;
        float pcx = __ldg(pr), pcy = __ldg(pr+1), pw = __ldg(pr+2), phh = __ldg(pr+3);
        float gcx = ((x0 + x1) * 0.5f - pcx) * 10.f / pw;
        float gcy = ((y0 + y1) * 0.5f - pcy) * 10.f / phh;
        float gw  = logf((x1 - x0) / pw) * 5.f;
        float gh  = logf((y1 - y0) / phh) * 5.f;
        const float* pd = pred + (size_t)idx * 4;
        l1 = fabsf(pd[0]-gcx) + fabsf(pd[1]-gcy) + fabsf(pd[2]-gw) + fabsf(pd[3]-gh);
    }
    int lane = threadIdx.x & 31, wid = threadIdx.x >> 5;
    #pragma unroll
    for (int off = 16; off; off >>= 1) {
        l1  += __shfl_xor_sync(0xffffffffu, l1, off);
        cnt += __shfl_xor_sync(0xffffffffu, cnt, off);
    }
    __shared__ float rl1[8]; __shared__ int rcnt[8];
    if (lane == 0) { rl1[wid] = l1; rcnt[wid] = cnt; }
    __syncthreads();
    if (threadIdx.x == 0) {
        float l = 0.f; int c = 0;
        #pragma unroll
        for (int i = 0; i < 8; i++) { l += rl1[i]; c += rcnt[i]; }
        if (l != 0.f) atomicAdd(&g_loc_sum, l);
        if (c)        atomicAdd(&g_npos, c);
    }
}

// ---------------- kA: persistent CE, TMA double-buffer, lean hot loop -----------
// Per iteration: ONE independent g_lab prefetch issued BEFORE the TMA wait (it
// completes under the wait), then lse + key store. No dependent-load chain.
__global__ void __launch_bounds__(TPA) kA_ce(const float* __restrict__ scores) {
    __shared__ alignas(128) float buf[2][TROWS * CC];   // 2 x 20736 B
    __shared__ alignas(8) unsigned long long mbar[2];
    __shared__ float racc[8];
    int tid = threadIdx.x;
    int bid = blockIdx.x;
    int q = tid & 3;            // quarter within row
    int r = tid >> 2;           // row within tile (0..63)

    unsigned mb[2], sb[2];
    mb[0] = (unsigned)__cvta_generic_to_shared(&mbar[0]);
    mb[1] = (unsigned)__cvta_generic_to_shared(&mbar[1]);
    sb[0] = (unsigned)__cvta_generic_to_shared(buf[0]);
    sb[1] = (unsigned)__cvta_generic_to_shared(buf[1]);

    if (tid == 0) { mbar_init(mb[0], 1); mbar_init(mb[1], 1); }
    __syncthreads();

    if (tid == 0) {   // prologue: both stages (bid, bid+GRID_A < NTILES since bid<740)
        mbar_expect_tx(mb[0], TILE_B);
        bulk_g2s(sb[0], (const char*)scores + (size_t)bid * TILE_B, TILE_B, mb[0]);
        mbar_expect_tx(mb[1], TILE_B);
        bulk_g2s(sb[1], (const char*)scores + (size_t)(bid + GRID_A) * TILE_B,
                 TILE_B, mb[1]);
    }

    float acc = 0.f;
    int ph[2] = {0, 0};
    int i = 0;
    for (int t = bid; t < NTILES; t += GRID_A, i++) {
        int s = i & 1;
        int idx = t * TROWS + r;
        int lab = 0;
        if (q == 0) lab = __ldg(g_lab + idx);   // independent; lands under the wait

        mbar_wait(mb[s], ph[s]);
        ph[s] ^= 1;

        const float* my = buf[s] + r * CC;
        int base = q * 20;
        float a0 = 0.f, a1 = 0.f, a2 = 0.f, a3 = 0.f;
        #pragma unroll
        for (int j = 0; j < 20; j += 4) {
            a0 += __expf(my[base + j]);
            a1 += __expf(my[base + j + 1]);
            a2 += __expf(my[base + j + 2]);
            a3 += __expf(my[base + j + 3]);
        }
        float e = (a0 + a1) + (a2 + a3);
        if (q == 3) e += __expf(my[80]);
        e += __shfl_xor_sync(0xffffffffu, e, 1);
        e += __shfl_xor_sync(0xffffffffu, e, 2);   // all 4 quarters have full sum

        if (q == 0) {
            float ce = __logf(e) - my[lab];        // label score straight from smem
            g_key[idx] = order_key(ce);
            if (lab != 0) acc += ce;
        }
        __syncthreads();               // all threads done reading buf[s]
        int t2 = t + 2 * GRID_A;
        if (t2 < NTILES && tid == 0) { // re-arm stage s
            mbar_expect_tx(mb[s], TILE_B);
            bulk_g2s(sb[s], (const char*)scores + (size_t)t2 * TILE_B, TILE_B, mb[s]);
        }
    }

    // block reduce once at the end
    int lane = tid & 31, wid = tid >> 5;
    #pragma unroll
    for (int off = 16; off; off >>= 1)
        acc += __shfl_xor_sync(0xffffffffu, acc, off);
    if (lane == 0) racc[wid] = acc;
    __syncthreads();
    if (tid == 0) {
        float a = 0.f;
        #pragma unroll
        for (int j = 0; j < 8; j++) a += racc[j];
        if (a != 0.f) atomicAdd(&g_cepos, a);
    }
}

// ---------------- kD: per-row top-k via radix select + fused finalize -----------
__global__ void __launch_bounds__(1024) kD_select(float* __restrict__ out) {
    __shared__ unsigned skeys[PP];
    __shared__ int bins[256];
    __shared__ unsigned sh_pref;
    __shared__ int sh_rem;
    __shared__ float swsum[32];
    __shared__ int swcnt[32];
    int r = blockIdx.x;
    int tid = threadIdx.x;
    const int bd = 1024;
    int lane = tid & 31, wid = tid >> 5;

    {   // uint4 loads: PP = 4*2183
        const uint4* src = (const uint4*)(g_key + (size_t)r * PP);
        uint4* dst = (uint4*)skeys;
        for (int i = tid; i < PP/4; i += bd) dst[i] = src[i];
    }
    __syncthreads();
    int np = g_npos;
    long long k = 3LL * (long long)np;
    const int NITER = (PP + bd - 1) / bd;    // 9 padded iterations (warp-uniform)

    float total = 0.f;
    if (k >= PP) {
        float sv = 0.f;
        for (int p = tid; p < PP; p += bd) sv += key_val(skeys[p]);
        #pragma unroll
        for (int off = 16; off; off >>= 1) sv += __shfl_xor_sync(0xffffffffu, sv, off);
        if (lane == 0) swsum[wid] = sv;
        __syncthreads();
        if (tid == 0) for (int i = 0; i < 32; i++) total += swsum[i];
    } else if (k > 0) {
        unsigned prefix = 0; int rem = (int)k;
        for (int shift = 24; shift >= 0; shift -= 8) {
            if (tid < 256) bins[tid] = 0;
            __syncthreads();
            unsigned hi_mask = (shift == 24) ? 0u : (0xFFFFFFFFu << (shift + 8));
            for (int it = 0; it < NITER; it++) {
                int p = tid + it * bd;
                bool in = (p < PP);
                unsigned key = in ? skeys[p] : 0u;
                bool act = in && ((key & hi_mask) == prefix);
                unsigned bm = __ballot_sync(0xffffffffu, act);
                if (act) {
                    unsigned bin = (key >> shift) & 255u;
                    unsigned peers = __match_any_sync(bm, bin);
                    int leader = __ffs(peers) - 1;
                    if (lane == leader) atomicAdd(&bins[bin], __popc(peers));
                }
            }
            __syncthreads();
            if (tid < 32) {                       // warp-0 suffix scan, 8 bins/lane
                int v[8]; int t = 0;
                #pragma unroll
                for (int j = 0; j < 8; j++) { v[j] = bins[tid*8 + j]; t += v[j]; }
                int run = t;
                #pragma unroll
                for (int off = 1; off < 32; off <<= 1) {
                    int x = __shfl_down_sync(0xffffffffu, run, off);
                    if (tid + off < 32) run += x;
                }
                int c = run - t;                  // suffix over lanes > tid
                #pragma unroll
                for (int j = 7; j >= 0; j--) {
                    int prev = c;
                    c += v[j];
                    if (c >= rem && prev < rem) { // exactly one (lane,j) fires
                        sh_pref = prefix | ((unsigned)(tid*8 + j) << shift);
                        sh_rem  = rem - prev;
                    }
                }
            }
            __syncthreads();
            prefix = sh_pref; rem = sh_rem;
            __syncthreads();
        }
        unsigned kth = prefix;  // exact k-th largest key
        float sumv = 0.f; int cgt = 0;
        for (int p = tid; p < PP; p += bd) {
            unsigned key = skeys[p];
            if (key > kth) { sumv += key_val(key); cgt++; }
        }
        #pragma unroll
        for (int off = 16; off; off >>= 1) {
            sumv += __shfl_xor_sync(0xffffffffu, sumv, off);
            cgt  += __shfl_xor_sync(0xffffffffu, cgt, off);
        }
        if (lane == 0) { swsum[wid] = sumv; swcnt[wid] = cgt; }
        __syncthreads();
        if (tid == 0) {
            float t = 0.f; int c = 0;
            for (int i = 0; i < 32; i++) { t += swsum[i]; c += swcnt[i]; }
            total = t + (float)(k - c) * key_val(kth);   // exact tie handling
        }
    }

    if (tid == 0) {
        if (total != 0.f) atomicAdd(&g_hard, total);
        __threadfence();
        int ticket = atomicAdd(&g_done, 1);
        if (ticket == BB - 1) {                          // last block finalizes
            float hard = *(volatile float*)&g_hard;
            float npf = (float)np;
            out[0] = g_loc_sum / (npf * 4.f) + (g_cepos + hard) / npf;
        }
    }
}

// ---------------- launch ----------------
extern "C" void kernel_launch(void* const* d_in, const int* in_sizes, int n_in,
                              void* d_out, int out_size) {
    const float* pred_boxes   = (const float*)d_in[0];
    const float* pred_scores  = (const float*)d_in[1];
    const float* true_boxes   = (const float*)d_in[2];
    const int*   true_classes = (const int*)d_in[3];
    const float* pboxes       = (const float*)d_in[4];
    float* out = (float*)d_out;
    (void)in_sizes; (void)n_in; (void)out_size;

    k1_match<<<BB*NBLK1, 256>>>(true_boxes, pboxes, pred_scores);
    kB_scatter<<<2, 1024>>>();
    kC_label<<<(BB*PP)/256, 256>>>(pred_boxes, true_classes, true_boxes, pboxes);
    kA_ce<<<GRID_A, TPA>>>(pred_scores);
    kD_select<<<BB, 1024>>>(out);
}